// round 5
// baseline (speedup 1.0000x reference)
#include <cuda_runtime.h>
#include <cuda_bf16.h>

// Problem constants (x is [B=4096, T=512, D=4], batch_first)
#define H       32
#define DIN     4
#define GROWS   128      // 4*H gate rows
#define EPB     8        // batch elements per block
#define NTHREADS 512     // 128 threads per element-pair
#define CHUNK   32       // x timesteps staged per smem chunk
#define WPAD    36       // padded row stride (floats) for 32-wide weight rows

// smem layout (floats):
//   wih0  : 128*4         = 512
//   whh0  : 128*36        = 4608
//   wih1  : 128*36        = 4608
//   whh1  : 128*36        = 4608
//   h1    : 2*EPB*32      = 512   (double buffered)
//   h2    : 2*EPB*32      = 512
//   xbuf  : EPB*CHUNK*4   = 1024
#define SM_FLOATS (512 + 3*4608 + 2*(2*EPB*32) + EPB*CHUNK*4)
#define SM_BYTES  (SM_FLOATS * 4)

__device__ __forceinline__ float sigf(float x) {
    return 1.0f / (1.0f + __expf(-x));
}
__device__ __forceinline__ float tanhfast(float x) {
    return 2.0f / (1.0f + __expf(-2.0f * x)) - 1.0f;
}

__global__ __launch_bounds__(NTHREADS, 1)
void lstm2_kernel(const float* __restrict__ x,
                  const float* __restrict__ Wih0, const float* __restrict__ Whh0,
                  const float* __restrict__ bih0, const float* __restrict__ bhh0,
                  const float* __restrict__ Wih1, const float* __restrict__ Whh1,
                  const float* __restrict__ bih1, const float* __restrict__ bhh1,
                  const float* __restrict__ Wout, const float* __restrict__ bout,
                  float* __restrict__ out, int T)
{
    extern __shared__ float sm[];
    float* s_wih0 = sm;                       // [128][4]
    float* s_whh0 = s_wih0 + 512;             // [128][36]
    float* s_wih1 = s_whh0 + 128 * WPAD;      // [128][36]
    float* s_whh1 = s_wih1 + 128 * WPAD;      // [128][36]
    float* s_h1   = s_whh1 + 128 * WPAD;      // [2][EPB][32]
    float* s_h2   = s_h1 + 2 * EPB * 32;      // [2][EPB][32]
    float* s_x    = s_h2 + 2 * EPB * 32;      // [EPB][CHUNK][4]

    const int tid = threadIdx.x;
    const int b0  = blockIdx.x * EPB;

    // ---- stage weights into smem (one time) ----
    for (int i = tid; i < 512; i += NTHREADS) s_wih0[i] = Wih0[i];
    for (int i = tid; i < 4096; i += NTHREADS) {
        int r = i >> 5, k = i & 31;
        s_whh0[r * WPAD + k] = Whh0[i];
        s_wih1[r * WPAD + k] = Wih1[i];
        s_whh1[r * WPAD + k] = Whh1[i];
    }
    // zero h state (h1 and h2 are contiguous: 4*EPB*32 floats)
    for (int i = tid; i < 4 * EPB * 32; i += NTHREADS) s_h1[i] = 0.0f;

    // ---- thread -> gate-row mapping ----
    // pair pr handles batch elements {2pr, 2pr+1}; within the 128 threads of a
    // pair: warp w4 owns hidden units [8*w4, 8*w4+8), lane l: gate gi = l>>3,
    // hidden jj = 8*w4 + (l&7). All 4 gates of a hidden unit live in one warp.
    const int pr = tid >> 7;
    const int wt = tid & 127;
    const int w4 = wt >> 5;
    const int l  = wt & 31;
    const int gi = l >> 3;
    const int jj = (w4 << 3) + (l & 7);
    const int r  = (gi << 5) + jj;          // gate row 0..127
    const int e0 = pr * 2, e1 = e0 + 1;

    const float bias0 = bih0[r] + bhh0[r];
    const float bias1 = bih1[r] + bhh1[r];

    // ---- prefetch first x chunk into registers ----
    // chunk = EPB*CHUNK*4 = 1024 floats = 2*NTHREADS
    float xr0, xr1;
    {
        int i0 = tid, i1 = tid + NTHREADS;
        xr0 = x[(b0 + (i0 >> 7)) * (T * DIN) + (i0 & 127)];
        xr1 = x[(b0 + (i1 >> 7)) * (T * DIN) + (i1 & 127)];
    }

    float cA0 = 0.f, cA1 = 0.f;   // layer0 cell state (valid in lanes l<8)
    float cB0 = 0.f, cB1 = 0.f;   // layer1 cell state
    int p = 0;

    __syncthreads();

    for (int t = 0; t < T; ++t) {
        const int ts = t & (CHUNK - 1);
        if (ts == 0) {
            // commit prefetched chunk, then prefetch the next one
            s_x[tid] = xr0;
            s_x[tid + NTHREADS] = xr1;
            __syncthreads();
            int tn = t + CHUNK;
            if (tn < T) {
                int i0 = tid, i1 = tid + NTHREADS;
                xr0 = x[(b0 + (i0 >> 7)) * (T * DIN) + tn * DIN + (i0 & 127)];
                xr1 = x[(b0 + (i1 >> 7)) * (T * DIN) + tn * DIN + (i1 & 127)];
            }
        }
        const int q = p ^ 1;

        // ================= layer 0 =================
        float a0 = bias0, a1 = bias0;
        {
            float4 w  = *(const float4*)(s_wih0 + (r << 2));
            float4 xa = *(const float4*)(s_x + (e0 << 7) + (ts << 2));
            float4 xb = *(const float4*)(s_x + (e1 << 7) + (ts << 2));
            a0 = fmaf(w.x, xa.x, a0); a0 = fmaf(w.y, xa.y, a0);
            a0 = fmaf(w.z, xa.z, a0); a0 = fmaf(w.w, xa.w, a0);
            a1 = fmaf(w.x, xb.x, a1); a1 = fmaf(w.y, xb.y, a1);
            a1 = fmaf(w.z, xb.z, a1); a1 = fmaf(w.w, xb.w, a1);

            const float4* wr = (const float4*)(s_whh0 + r * WPAD);
            const float4* hA = (const float4*)(s_h1 + ((p * EPB + e0) << 5));
            const float4* hB = (const float4*)(s_h1 + ((p * EPB + e1) << 5));
#pragma unroll
            for (int kk = 0; kk < 8; ++kk) {
                float4 wv = wr[kk];
                float4 ha = hA[kk];
                float4 hb = hB[kk];
                a0 = fmaf(wv.x, ha.x, a0); a0 = fmaf(wv.y, ha.y, a0);
                a0 = fmaf(wv.z, ha.z, a0); a0 = fmaf(wv.w, ha.w, a0);
                a1 = fmaf(wv.x, hb.x, a1); a1 = fmaf(wv.y, hb.y, a1);
                a1 = fmaf(wv.z, hb.z, a1); a1 = fmaf(wv.w, hb.w, a1);
            }
        }
        float g0 = (gi == 2) ? tanhfast(a0) : sigf(a0);
        float g1 = (gi == 2) ? tanhfast(a1) : sigf(a1);

        // gather f,g,o into the i-gate lanes (l<8) of each hidden octet
        float f0  = __shfl_sync(0xffffffffu, g0, (l & 7) + 8);
        float gg0 = __shfl_sync(0xffffffffu, g0, (l & 7) + 16);
        float o0  = __shfl_sync(0xffffffffu, g0, (l & 7) + 24);
        float f1  = __shfl_sync(0xffffffffu, g1, (l & 7) + 8);
        float gg1 = __shfl_sync(0xffffffffu, g1, (l & 7) + 16);
        float o1  = __shfl_sync(0xffffffffu, g1, (l & 7) + 24);
        if (l < 8) {  // these lanes hold the i gate (gi==0)
            cA0 = fmaf(f0, cA0, g0 * gg0);
            s_h1[((q * EPB + e0) << 5) + jj] = o0 * tanhfast(cA0);
            cA1 = fmaf(f1, cA1, g1 * gg1);
            s_h1[((q * EPB + e1) << 5) + jj] = o1 * tanhfast(cA1);
        }
        __syncthreads();

        // ================= layer 1 =================
        a0 = bias1; a1 = bias1;
        {
            const float4* wi  = (const float4*)(s_wih1 + r * WPAD);
            const float4* wh  = (const float4*)(s_whh1 + r * WPAD);
            const float4* iA  = (const float4*)(s_h1 + ((q * EPB + e0) << 5)); // new h1
            const float4* iB  = (const float4*)(s_h1 + ((q * EPB + e1) << 5));
            const float4* hA  = (const float4*)(s_h2 + ((p * EPB + e0) << 5)); // old h2
            const float4* hB  = (const float4*)(s_h2 + ((p * EPB + e1) << 5));
#pragma unroll
            for (int kk = 0; kk < 8; ++kk) {
                float4 wv = wi[kk];
                float4 ha = iA[kk];
                float4 hb = iB[kk];
                a0 = fmaf(wv.x, ha.x, a0); a0 = fmaf(wv.y, ha.y, a0);
                a0 = fmaf(wv.z, ha.z, a0); a0 = fmaf(wv.w, ha.w, a0);
                a1 = fmaf(wv.x, hb.x, a1); a1 = fmaf(wv.y, hb.y, a1);
                a1 = fmaf(wv.z, hb.z, a1); a1 = fmaf(wv.w, hb.w, a1);
                float4 wv2 = wh[kk];
                float4 ga = hA[kk];
                float4 gb = hB[kk];
                a0 = fmaf(wv2.x, ga.x, a0); a0 = fmaf(wv2.y, ga.y, a0);
                a0 = fmaf(wv2.z, ga.z, a0); a0 = fmaf(wv2.w, ga.w, a0);
                a1 = fmaf(wv2.x, gb.x, a1); a1 = fmaf(wv2.y, gb.y, a1);
                a1 = fmaf(wv2.z, gb.z, a1); a1 = fmaf(wv2.w, gb.w, a1);
            }
        }
        g0 = (gi == 2) ? tanhfast(a0) : sigf(a0);
        g1 = (gi == 2) ? tanhfast(a1) : sigf(a1);
        f0  = __shfl_sync(0xffffffffu, g0, (l & 7) + 8);
        gg0 = __shfl_sync(0xffffffffu, g0, (l & 7) + 16);
        o0  = __shfl_sync(0xffffffffu, g0, (l & 7) + 24);
        f1  = __shfl_sync(0xffffffffu, g1, (l & 7) + 8);
        gg1 = __shfl_sync(0xffffffffu, g1, (l & 7) + 16);
        o1  = __shfl_sync(0xffffffffu, g1, (l & 7) + 24);
        if (l < 8) {
            cB0 = fmaf(f0, cB0, g0 * gg0);
            s_h2[((q * EPB + e0) << 5) + jj] = o0 * tanhfast(cB0);
            cB1 = fmaf(f1, cB1, g1 * gg1);
            s_h2[((q * EPB + e1) << 5) + jj] = o1 * tanhfast(cB1);
        }
        __syncthreads();

        p = q;
    }

    // ---- final projection: out[b] = h2_final . Wout + bout ----
    // T even -> final h2 lives in buffer p (post-loop value)
    const int warp = tid >> 5;
    const int lane = tid & 31;
    if (warp < EPB) {
        float v = s_h2[((p * EPB + warp) << 5) + lane] * Wout[lane];
#pragma unroll
        for (int off = 16; off; off >>= 1)
            v += __shfl_xor_sync(0xffffffffu, v, off);
        if (lane == 0) out[b0 + warp] = v + bout[0];
    }
}

extern "C" void kernel_launch(void* const* d_in, const int* in_sizes, int n_in,
                              void* d_out, int out_size)
{
    const float* x    = (const float*)d_in[0];
    const float* Wih0 = (const float*)d_in[1];
    const float* Whh0 = (const float*)d_in[2];
    const float* bih0 = (const float*)d_in[3];
    const float* bhh0 = (const float*)d_in[4];
    const float* Wih1 = (const float*)d_in[5];
    const float* Whh1 = (const float*)d_in[6];
    const float* bih1 = (const float*)d_in[7];
    const float* bhh1 = (const float*)d_in[8];
    const float* Wout = (const float*)d_in[9];
    const float* bout = (const float*)d_in[10];
    float* out = (float*)d_out;

    // x is [B, T, D] batch_first; output is [B, 1] -> B = out_size
    const int B = out_size;                       // 4096
    const int T = in_sizes[0] / (B * DIN);        // 512

    cudaFuncSetAttribute(lstm2_kernel,
                         cudaFuncAttributeMaxDynamicSharedMemorySize, SM_BYTES);
    lstm2_kernel<<<B / EPB, NTHREADS, SM_BYTES>>>(
        x, Wih0, Whh0, bih0, bhh0, Wih1, Whh1, bih1, bhh1, Wout, bout, out, T);
}